// round 12
// baseline (speedup 1.0000x reference)
#include <cuda_runtime.h>
#include <cuda_bf16.h>
#include <math.h>

#define MAXN 50000
#define MAXE 800000
#define EPS 1e-5f
#define NEG_SLOPE 0.2f

#define PS_THREADS 8192            // scan partition: 32 blocks x 256 threads
#define PS_PER_T   8               // pass-B serial factor (8192/1024)

// ---------------- scratch (device globals; no allocation allowed) ----------------
__device__ __align__(16) float g_P  [(size_t)MAXN * 128];   // h = x @ W^T
__device__ __align__(16) float g_ACC[(size_t)MAXN * 128];   // node features (layer output)
__device__ float    g_as [MAXN];
__device__ float    g_ad [MAXN];
__device__ int      g_src[MAXE];
__device__ int      g_dst[MAXE];
__device__ int      g_cnt[MAXN + 1];             // histogram -> CSR rowptr
__device__ int      g_pos[MAXN];                 // scatter cursor
__device__ int      g_esrc[MAXE + MAXN];         // src ids sorted by dst (self-loop first)
__device__ int      g_tsum[PS_THREADS];          // per-thread chunk sums / prefixes
__device__ float    g_st_s[3][128];              // per-layer BN column sums
__device__ float    g_st_q[3][128];              // per-layer BN column sumsq
__device__ int      g_is64;                      // edge_index dtype flag

// ---------------- setup kernels ----------------

__global__ void k_detect(const int* __restrict__ w) {
    if (threadIdx.x == 0 && blockIdx.x == 0) {
        int all_zero = 1;
        for (int i = 0; i < 64; i++)
            if (w[2 * i + 1] != 0) { all_zero = 0; break; }
        g_is64 = all_zero;
    }
}

__global__ void k_zero(int n) {
    int i = blockIdx.x * blockDim.x + threadIdx.x;
    if (i <= n) g_cnt[i] = 0;
    if (i < 3 * 128) { ((float*)g_st_s)[i] = 0.f; ((float*)g_st_q)[i] = 0.f; }
}

// convert edge dtype + histogram dst
__global__ void k_setup(const void* __restrict__ ei, int E) {
    int i = blockIdx.x * blockDim.x + threadIdx.x;
    if (i >= E) return;
    int s, d;
    if (g_is64) {
        const long long* p = (const long long*)ei;
        s = (int)p[i]; d = (int)p[(size_t)E + i];
    } else {
        const int* p = (const int*)ei;
        s = p[i]; d = p[(size_t)E + i];
    }
    g_src[i] = s; g_dst[i] = d;
    atomicAdd(&g_cnt[d], 1);
}

// ---- parallel CSR scan: A) per-thread chunk sums ----
__global__ void k_psum(int n) {
    int t = blockIdx.x * blockDim.x + threadIdx.x;
    int chunk = (n + PS_THREADS - 1) / PS_THREADS;
    int beg = t * chunk, end = min(beg + chunk, n);
    int sum = 0;
    for (int i = beg; i < end; i++) sum += g_cnt[i] + 1;   // +1 self-loop
    g_tsum[t] = sum;
}

// ---- B) exclusive scan of the 8192 chunk sums (1 block, 1024 threads) ----
__global__ void __launch_bounds__(1024) k_scant(int n) {
    __shared__ int partial[1024];
    int tid = threadIdx.x;
    int vals[PS_PER_T];
    int base = tid * PS_PER_T;
    int s = 0;
    #pragma unroll
    for (int j = 0; j < PS_PER_T; j++) { vals[j] = g_tsum[base + j]; s += vals[j]; }
    partial[tid] = s;
    __syncthreads();
    for (int off = 1; off < 1024; off <<= 1) {
        int v = (tid >= off) ? partial[tid - off] : 0;
        __syncthreads();
        partial[tid] += v;
        __syncthreads();
    }
    int run = tid ? partial[tid - 1] : 0;
    #pragma unroll
    for (int j = 0; j < PS_PER_T; j++) { g_tsum[base + j] = run; run += vals[j]; }
    if (tid == 1023) g_cnt[n] = partial[1023];
}

// ---- C) fill rowptr, self-loop slot, scatter cursor ----
__global__ void k_fill(int n) {
    int t = blockIdx.x * blockDim.x + threadIdx.x;
    int chunk = (n + PS_THREADS - 1) / PS_THREADS;
    int beg = t * chunk, end = min(beg + chunk, n);
    int run = g_tsum[t];
    for (int i = beg; i < end; i++) {
        int c = g_cnt[i] + 1;
        g_cnt[i] = run;          // rowptr
        g_esrc[run] = i;         // self-loop in first slot
        g_pos[i] = run + 1;
        run += c;
    }
}

__global__ void k_scatter(int E) {
    int i = blockIdx.x * blockDim.x + threadIdx.x;
    if (i >= E) return;
    int pos = atomicAdd(&g_pos[g_dst[i]], 1);
    g_esrc[pos] = g_src[i];
}

// ---------------- GEMM: h = bn(X) @ W^T ; alpha_s/alpha_d ----------------
template<int IN, int OUT, bool BN>
__global__ void __launch_bounds__(256) k_gemm(
        const float* __restrict__ Xin, const float* __restrict__ W,
        const float* __restrict__ asv, const float* __restrict__ adv,
        const float* __restrict__ gam, const float* __restrict__ bet,
        int slot, int n) {
    const float* X = Xin ? Xin : g_ACC;
    __shared__ float Wt[IN * OUT];
    __shared__ float xs[32 * IN];
    int tid = threadIdx.x;

    for (int i = tid; i < IN * OUT; i += 256) {
        int o = i / IN, k = i % IN;
        Wt[k * OUT + o] = W[i];
    }

    int row0 = blockIdx.x * 32;
    int nr = min(32, n - row0);
    const float4* Xv = (const float4*)(X + (size_t)row0 * IN);
    int tot4 = (nr * IN) >> 2;

    if constexpr (BN) {
        __shared__ float cs[IN], csh[IN];
        float inv_n = 1.f / (float)n;
        for (int i = tid; i < IN; i += 256) {
            float mu  = g_st_s[slot][i] * inv_n;
            float var = g_st_q[slot][i] * inv_n - mu * mu;
            float sc  = gam[i] * rsqrtf(var + EPS);
            cs[i]  = sc;
            csh[i] = bet[i] - mu * sc;
        }
        __syncthreads();
        for (int i = tid; i < tot4; i += 256) {
            float4 v = Xv[i];
            int c = (i * 4) & (IN - 1);
            v.x = fmaf(v.x, cs[c + 0], csh[c + 0]);
            v.y = fmaf(v.y, cs[c + 1], csh[c + 1]);
            v.z = fmaf(v.z, cs[c + 2], csh[c + 2]);
            v.w = fmaf(v.w, cs[c + 3], csh[c + 3]);
            ((float4*)xs)[i] = v;
        }
    } else {
        for (int i = tid; i < tot4; i += 256) ((float4*)xs)[i] = Xv[i];
    }
    __syncthreads();

    int warp = tid >> 5, lane = tid & 31;
    constexpr int OP = OUT / 32;
    float acc[4][OP];
    #pragma unroll
    for (int r = 0; r < 4; r++)
        #pragma unroll
        for (int p = 0; p < OP; p++) acc[r][p] = 0.f;

    const float* xb = &xs[(warp * 4) * IN];
    #pragma unroll 4
    for (int k4 = 0; k4 < IN / 4; k4++) {
        float4 xv[4];
        #pragma unroll
        for (int r = 0; r < 4; r++)
            xv[r] = *(const float4*)&xb[r * IN + k4 * 4];
        #pragma unroll
        for (int kk = 0; kk < 4; kk++) {
            float wv[OP];
            if constexpr (OP == 2) {
                float2 t = *(const float2*)&Wt[(k4 * 4 + kk) * OUT + lane * 2];
                wv[0] = t.x; wv[1] = t.y;
            } else {
                float4 t = *(const float4*)&Wt[(k4 * 4 + kk) * OUT + lane * 4];
                wv[0] = t.x; wv[1] = t.y; wv[2] = t.z; wv[3] = t.w;
            }
            #pragma unroll
            for (int r = 0; r < 4; r++) {
                const float* xf = (const float*)&xv[r];
                float xvk = xf[kk];
                #pragma unroll
                for (int p = 0; p < OP; p++) acc[r][p] += xvk * wv[p];
            }
        }
    }

    float avs[OP], avd[OP];
    #pragma unroll
    for (int p = 0; p < OP; p++) {
        avs[p] = asv[lane * OP + p];
        avd[p] = adv[lane * OP + p];
    }

    #pragma unroll
    for (int r = 0; r < 4; r++) {
        int row = row0 + warp * 4 + r;
        if (row >= n) break;
        if constexpr (OP == 2) {
            *(float2*)&g_P[(size_t)row * OUT + lane * 2] = make_float2(acc[r][0], acc[r][1]);
        } else {
            *(float4*)&g_P[(size_t)row * OUT + lane * 4] =
                make_float4(acc[r][0], acc[r][1], acc[r][2], acc[r][3]);
        }
        float sA = 0.f, sD = 0.f;
        #pragma unroll
        for (int p = 0; p < OP; p++) { sA += acc[r][p] * avs[p]; sD += acc[r][p] * avd[p]; }
        #pragma unroll
        for (int off = 16; off; off >>= 1) {
            sA += __shfl_xor_sync(0xffffffffu, sA, off);
            sD += __shfl_xor_sync(0xffffffffu, sD, off);
        }
        if (lane == 0) { g_as[row] = sA; g_ad[row] = sD; }
    }
}

// ---------------- CSR edge pass, F=64: ONE WARP PER NODE ----------------
// lane holds float2 of the row (32*8B = 256B, coalesced). 4-wide edge unroll.
// No BN stats here (separate k_stats) -> no block-level sync, no tail stretch.
__global__ void __launch_bounds__(256) k_edge64(const float* __restrict__ bias, int n) {
    int tid = threadIdx.x;
    int node = (blockIdx.x * 256 + tid) >> 5;
    if (node >= n) return;
    int lane = tid & 31;
    const float2* __restrict__ P2 = (const float2*)g_P;

    int beg = g_cnt[node], end = g_cnt[node + 1];
    float ad = g_ad[node];
    float ax = 0.f, ay = 0.f, wsum = 0.f;
    int e = beg;
    for (; e + 4 <= end; e += 4) {
        int s0 = g_esrc[e], s1 = g_esrc[e + 1], s2 = g_esrc[e + 2], s3 = g_esrc[e + 3];
        float a0 = g_as[s0], a1 = g_as[s1], a2 = g_as[s2], a3 = g_as[s3];
        float2 v0 = P2[(size_t)s0 * 32 + lane];
        float2 v1 = P2[(size_t)s1 * 32 + lane];
        float2 v2 = P2[(size_t)s2 * 32 + lane];
        float2 v3 = P2[(size_t)s3 * 32 + lane];
        float e0 = a0 + ad; e0 = e0 > 0.f ? e0 : NEG_SLOPE * e0;
        float e1 = a1 + ad; e1 = e1 > 0.f ? e1 : NEG_SLOPE * e1;
        float e2 = a2 + ad; e2 = e2 > 0.f ? e2 : NEG_SLOPE * e2;
        float e3 = a3 + ad; e3 = e3 > 0.f ? e3 : NEG_SLOPE * e3;
        float w0 = __expf(e0), w1 = __expf(e1), w2 = __expf(e2), w3 = __expf(e3);
        wsum += (w0 + w1) + (w2 + w3);
        ax = fmaf(w0, v0.x, fmaf(w1, v1.x, fmaf(w2, v2.x, fmaf(w3, v3.x, ax))));
        ay = fmaf(w0, v0.y, fmaf(w1, v1.y, fmaf(w2, v2.y, fmaf(w3, v3.y, ay))));
    }
    for (; e < end; e++) {
        int s0 = g_esrc[e];
        float a0 = g_as[s0];
        float2 v0 = P2[(size_t)s0 * 32 + lane];
        float e0 = a0 + ad; e0 = e0 > 0.f ? e0 : NEG_SLOPE * e0;
        float w0 = __expf(e0);
        wsum += w0;
        ax = fmaf(w0, v0.x, ax); ay = fmaf(w0, v0.y, ay);
    }
    float inv = 1.f / (wsum + 1e-16f);
    float2 bv = ((const float2*)bias)[lane];
    float2 r;
    r.x = fmaxf(fmaf(ax, inv, bv.x), 0.f);
    r.y = fmaxf(fmaf(ay, inv, bv.y), 0.f);
    ((float2*)g_ACC)[(size_t)node * 32 + lane] = r;
}

// BN column stats over ACC (F=64). blockDim=64, one thread per column.
__global__ void k_stats(int slot, int n) {
    int f = threadIdx.x;
    float sum = 0.f, sq = 0.f;
    for (int row = blockIdx.x; row < n; row += gridDim.x) {
        float v = g_ACC[(size_t)row * 64 + f];
        sum += v; sq += v * v;
    }
    atomicAdd(&g_st_s[slot][f], sum);
    atomicAdd(&g_st_q[slot][f], sq);
}

// ---------------- final edge pass, F=128: one warp per node, fused output ----
__global__ void __launch_bounds__(256) k_edge128(
        const float* __restrict__ bias, const float* __restrict__ x,
        float* __restrict__ out, int n) {
    int tid = threadIdx.x;
    int node = (blockIdx.x * 256 + tid) >> 5;
    if (node >= n) return;
    int lane = tid & 31;
    const float4* __restrict__ P4 = (const float4*)g_P;

    int beg = g_cnt[node], end = g_cnt[node + 1];
    float ad = g_ad[node];
    float ax = 0.f, ay = 0.f, az = 0.f, aw = 0.f, wsum = 0.f;
    int e = beg;
    for (; e + 2 <= end; e += 2) {
        int s0 = g_esrc[e], s1 = g_esrc[e + 1];
        float a0 = g_as[s0], a1 = g_as[s1];
        float4 v0 = P4[(size_t)s0 * 32 + lane];
        float4 v1 = P4[(size_t)s1 * 32 + lane];
        float e0 = a0 + ad; e0 = e0 > 0.f ? e0 : NEG_SLOPE * e0;
        float e1 = a1 + ad; e1 = e1 > 0.f ? e1 : NEG_SLOPE * e1;
        float w0 = __expf(e0), w1 = __expf(e1);
        wsum += w0 + w1;
        ax = fmaf(w0, v0.x, fmaf(w1, v1.x, ax));
        ay = fmaf(w0, v0.y, fmaf(w1, v1.y, ay));
        az = fmaf(w0, v0.z, fmaf(w1, v1.z, az));
        aw = fmaf(w0, v0.w, fmaf(w1, v1.w, aw));
    }
    if (e < end) {
        int s0 = g_esrc[e];
        float a0 = g_as[s0];
        float4 v0 = P4[(size_t)s0 * 32 + lane];
        float e0 = a0 + ad; e0 = e0 > 0.f ? e0 : NEG_SLOPE * e0;
        float w0 = __expf(e0);
        wsum += w0;
        ax = fmaf(w0, v0.x, ax); ay = fmaf(w0, v0.y, ay);
        az = fmaf(w0, v0.z, az); aw = fmaf(w0, v0.w, aw);
    }
    float inv = 1.f / (wsum + 1e-16f);
    float4 bv = ((const float4*)bias)[lane];
    float4 xh;
    xh.x = fmaxf(fmaf(ax, inv, bv.x), 0.f);
    xh.y = fmaxf(fmaf(ay, inv, bv.y), 0.f);
    xh.z = fmaxf(fmaf(az, inv, bv.z), 0.f);
    xh.w = fmaxf(fmaf(aw, inv, bv.w), 0.f);
    size_t o = (size_t)node * 32 + lane;
    float4 xv = ((const float4*)x)[o];
    float4 df;
    df.x = fabsf(xv.x - xh.x); df.y = fabsf(xv.y - xh.y);
    df.z = fabsf(xv.z - xh.z); df.w = fabsf(xv.w - xh.w);
    ((float4*)out)[o] = df;
    ((float4*)out)[(size_t)n * 32 + o] = xh;
}

// ---------------- launch ----------------
extern "C" void kernel_launch(void* const* d_in, const int* in_sizes, int n_in,
                              void* d_out, int out_size) {
    const float* x   = (const float*)d_in[0];
    const void*  ei  = d_in[1];
    const float* W1  = (const float*)d_in[2];
    const float* a1s = (const float*)d_in[3];
    const float* a1d = (const float*)d_in[4];
    const float* b1  = (const float*)d_in[5];
    const float* g1  = (const float*)d_in[6];
    const float* be1 = (const float*)d_in[7];
    const float* W2  = (const float*)d_in[8];
    const float* a2s = (const float*)d_in[9];
    const float* a2d = (const float*)d_in[10];
    const float* b2  = (const float*)d_in[11];
    const float* g2  = (const float*)d_in[12];
    const float* be2 = (const float*)d_in[13];
    const float* W3  = (const float*)d_in[14];
    const float* a3s = (const float*)d_in[15];
    const float* a3d = (const float*)d_in[16];
    const float* b3  = (const float*)d_in[17];
    const float* g3  = (const float*)d_in[18];
    const float* be3 = (const float*)d_in[19];
    const float* W4  = (const float*)d_in[20];
    const float* a4s = (const float*)d_in[21];
    const float* a4d = (const float*)d_in[22];
    const float* b4  = (const float*)d_in[23];
    float* out = (float*)d_out;

    int n = in_sizes[0] / 128;     // 50000
    int E = in_sizes[1] / 2;       // 800000

    const int TB = 256;
    int cb = (E + TB - 1) / TB;
    int gb = (n + 31) / 32;
    int zb = (n + 1 + TB - 1) / TB;
    int wb = (n * 32 + TB - 1) / TB;     // one warp per node

    // CSR build (once per launch) — parallel scan
    k_detect<<<1, 32>>>((const int*)ei);
    k_zero<<<zb, TB>>>(n);
    k_setup<<<cb, TB>>>(ei, E);
    k_psum<<<PS_THREADS / TB, TB>>>(n);
    k_scant<<<1, 1024>>>(n);
    k_fill<<<PS_THREADS / TB, TB>>>(n);
    k_scatter<<<cb, TB>>>(E);

    // ---- layer 1: 128 -> 64 ----
    k_gemm<128, 64, false><<<gb, 256>>>(x, W1, a1s, a1d, nullptr, nullptr, 0, n);
    k_edge64<<<wb, TB>>>(b1, n);
    k_stats<<<1184, 64>>>(0, n);

    // ---- layer 2: 64 -> 64 (BN of layer1 fused, stats slot 0) ----
    k_gemm<64, 64, true><<<gb, 256>>>(nullptr, W2, a2s, a2d, g1, be1, 0, n);
    k_edge64<<<wb, TB>>>(b2, n);
    k_stats<<<1184, 64>>>(1, n);

    // ---- layer 3: 64 -> 64 ----
    k_gemm<64, 64, true><<<gb, 256>>>(nullptr, W3, a3s, a3d, g2, be2, 1, n);
    k_edge64<<<wb, TB>>>(b3, n);
    k_stats<<<1184, 64>>>(2, n);

    // ---- layer 4: 64 -> 128, fused final output ----
    k_gemm<64, 128, true><<<gb, 256>>>(nullptr, W4, a4s, a4d, g3, be3, 2, n);
    k_edge128<<<wb, TB>>>(b4, x, out, n);
}